// round 15
// baseline (speedup 1.0000x reference)
#include <cuda_runtime.h>
#include <math.h>

#define D_IN     256
#define D_OUT    64
#define THREADS  160          // 4 compute warps (64 rows) + 1 setup warp
#define ROWS     64
#define WAVE     740          // one residency wave (148 SM x 5 blocks)
#define PI_F     3.14159265358979323846f

typedef unsigned long long u64;

// ---- packed f32x2 helpers (sm_100+) ---------------------------------------
static __device__ __forceinline__ u64 ffma2(u64 a, u64 b, u64 c) {
    u64 d; asm("fma.rn.f32x2 %0, %1, %2, %3;" : "=l"(d) : "l"(a), "l"(b), "l"(c)); return d;
}
static __device__ __forceinline__ u64 fadd2(u64 a, u64 b) {
    u64 d; asm("add.rn.f32x2 %0, %1, %2;" : "=l"(d) : "l"(a), "l"(b)); return d;
}
static __device__ __forceinline__ u64 pack2(float lo, float hi) {
    u64 d; asm("mov.b64 %0, {%1, %2};" : "=l"(d) : "f"(lo), "f"(hi)); return d;
}
static __device__ __forceinline__ void unpack2(u64 v, float& lo, float& hi) {
    asm("mov.b64 {%0, %1}, %2;" : "=f"(lo), "=f"(hi) : "l"(v));
}
static __device__ __forceinline__ float2 cmulf(float2 a, float2 b) {
    return make_float2(a.x * b.x - a.y * b.y, a.x * b.y + a.y * b.x);
}
static __device__ __forceinline__ float2 cmac2(float2 a, float2 b, float2 c, float2 d) {
    float re = a.x * b.x - a.y * b.y + c.x * d.x - c.y * d.y;
    float im = a.x * b.y + a.y * b.x + c.x * d.y + c.y * d.x;
    return make_float2(re, im);
}

// phase-1 helpers as macros (straightline, compile-time indices only)
#define LOAD_PAIR(B0, B1, MP)                                                 \
    do {                                                                      \
        _Pragma("unroll")                                                     \
        for (int r = 0; r < 4; r++) {                                         \
            B0[r] = make_float4(0.f, 0.f, 0.f, 0.f);                          \
            B1[r] = make_float4(0.f, 0.f, 0.f, 0.f);                          \
            if (ok[r]) {                                                      \
                const float* rp = xb + (size_t)(r * 4) * D_IN;                \
                B0[r] = __ldg((const float4*)(rp + (2 * (MP)) * 32));         \
                B1[r] = __ldg((const float4*)(rp + (2 * (MP) + 1) * 32));     \
            }                                                                 \
        }                                                                     \
    } while (0)

#define COMP_STEP(BUF, M)                                                     \
    do {                                                                      \
        const int c2 = (M) * 16 + j * 2;                                      \
        double2 wA = wps[0][c2], wA1 = wps[0][c2 + 1];                        \
        double2 wB = wps[1][c2], wB1 = wps[1][c2 + 1];                        \
        u64 w01_0 = __double_as_longlong(wA.x),  w01_1 = __double_as_longlong(wA.y);  \
        u64 w01_2 = __double_as_longlong(wA1.x), w01_3 = __double_as_longlong(wA1.y); \
        u64 w23_0 = __double_as_longlong(wB.x),  w23_1 = __double_as_longlong(wB.y);  \
        u64 w23_2 = __double_as_longlong(wB1.x), w23_3 = __double_as_longlong(wB1.y); \
        _Pragma("unroll")                                                     \
        for (int r = 0; r < 4; r++) {                                         \
            float4 xv = BUF[r];                                               \
            u64 x0 = pack2(xv.x, xv.x), x1 = pack2(xv.y, xv.y);               \
            u64 x2 = pack2(xv.z, xv.z), x3 = pack2(xv.w, xv.w);               \
            a01[r] = ffma2(x0, w01_0, a01[r]); a01[r] = ffma2(x1, w01_1, a01[r]); \
            a01[r] = ffma2(x2, w01_2, a01[r]); a01[r] = ffma2(x3, w01_3, a01[r]); \
            a23[r] = ffma2(x0, w23_0, a23[r]); a23[r] = ffma2(x1, w23_1, a23[r]); \
            a23[r] = ffma2(x2, w23_2, a23[r]); a23[r] = ffma2(x3, w23_3, a23[r]); \
        }                                                                     \
    } while (0)

// L2 prefetch of one warp's 16 rows of the given tile (4 lines/lane, no regs)
static __device__ __forceinline__ void l2_prefetch_tile(
    const float* __restrict__ x, int tile_row0, int rbase, int lane, int B)
{
    int row = tile_row0 + rbase + (lane >> 1);
    if (row < B) {
        const char* p = (const char*)(x + (size_t)row * D_IN) + (lane & 1) * 512;
        asm volatile("prefetch.global.L2 [%0];"     :: "l"(p));
        asm volatile("prefetch.global.L2 [%0+128];" :: "l"(p));
        asm volatile("prefetch.global.L2 [%0+256];" :: "l"(p));
        asm volatile("prefetch.global.L2 [%0+384];" :: "l"(p));
    }
}

// ---------------------------------------------------------------------------
// Fused kernel (one tile per block, balanced grid):
//   barrier A: wps ready. Between A and B: warp 4 builds usx || warps 0..3
//   run phase 1 (+ cross-wave L2 prefetch of tile b+WAVE) AND the usx-free
//   first half of phase 2 (encode + product state). barrier B gates ONLY the
//   usx matvec. Phase 3 warp-local; warp 4 returns.
// ---------------------------------------------------------------------------
__global__ __launch_bounds__(THREADS, 5)
void qproj_kernel(const float* __restrict__ x,  const float* __restrict__ W1,
                  const float* __restrict__ b1, const float* __restrict__ weights,
                  const float* __restrict__ W2, const float* __restrict__ b2,
                  float* __restrict__ out, int B, int n_layers)
{
    __shared__ double2 usx[256];      // expanded U: ((re,re),(im,im)), 4 KB
    __shared__ double2 wps[2][128];   // pair-packed W1, 2 KB
    __shared__ float4  fs[ROWS];      // pre-activation per row
    __shared__ float4  qs2[ROWS][2];  // partial <Z_i> per row, per half
    __shared__ float   b1s[4];

    const int t = threadIdx.x;
    if (t < 128) {
        // pair-packed weights: thread t owns columns 2t, 2t+1
        int c = t * 2;
        float a00 = __ldg(&W1[0 * D_IN + c]), a01 = __ldg(&W1[0 * D_IN + c + 1]);
        float a10 = __ldg(&W1[1 * D_IN + c]), a11 = __ldg(&W1[1 * D_IN + c + 1]);
        float a20 = __ldg(&W1[2 * D_IN + c]), a21 = __ldg(&W1[2 * D_IN + c + 1]);
        float a30 = __ldg(&W1[3 * D_IN + c]), a31 = __ldg(&W1[3 * D_IN + c + 1]);
        wps[0][t] = make_double2(__longlong_as_double((long long)pack2(a00, a10)),
                                 __longlong_as_double((long long)pack2(a01, a11)));
        wps[1][t] = make_double2(__longlong_as_double((long long)pack2(a20, a30)),
                                 __longlong_as_double((long long)pack2(a21, a31)));
        if (t < 4) b1s[t] = b1[t];
    }
    __syncthreads();                 // barrier A

    const int w    = t >> 5;         // warp id 0..4
    const int lane = t & 31;

    if (w == 4) {
        // =================== SETUP WARP: build usx =========================
        if (lane < 16) {
            const int j = lane;
            float2 uc[16];
            #pragma unroll
            for (int s = 0; s < 16; s++)
                uc[s] = make_float2(s == j ? 1.f : 0.f, 0.f);

            for (int l = 0; l < n_layers; l++) {
                const int SIG[16] = {0,6,12,10,11,13,7,1,15,9,3,5,4,2,8,14};
                float2 tv[16];
                #pragma unroll
                for (int s = 0; s < 16; s++) tv[s] = uc[SIG[s]];
                #pragma unroll
                for (int s = 0; s < 16; s++) uc[s] = tv[s];
                #pragma unroll
                for (int i = 0; i < 4; i++) {
                    float phi = __ldg(&weights[(l * 4 + i) * 3 + 0]);
                    float th  = __ldg(&weights[(l * 4 + i) * 3 + 1]);
                    float om  = __ldg(&weights[(l * 4 + i) * 3 + 2]);
                    float st, ct;  __sincosf(0.5f * th, &st, &ct);
                    float sa, ca;  __sincosf(0.5f * (phi + om), &sa, &ca);
                    float sb, cb;  __sincosf(0.5f * (phi - om), &sb, &cb);
                    float2 U00 = make_float2( ct * ca, -ct * sa);
                    float2 U01 = make_float2(-st * cb, -st * sb);
                    float2 U10 = make_float2( st * cb, -st * sb);
                    float2 U11 = make_float2( ct * ca,  ct * sa);
                    const int b = 3 - i, m = 1 << b;
                    #pragma unroll
                    for (int s = 0; s < 16; s++) {
                        if (!((s >> b) & 1)) {
                            float2 a0 = uc[s], a1 = uc[s | m];
                            uc[s]     = cmac2(U00, a0, U01, a1);
                            uc[s | m] = cmac2(U10, a0, U11, a1);
                        }
                    }
                }
            }
            #pragma unroll
            for (int s = 0; s < 16; s++)
                ((float4*)usx)[s * 16 + j] =
                    make_float4(uc[s].x, uc[s].x, uc[s].y, uc[s].y);
        }
        __syncthreads();             // barrier B: usx published
        return;
    }

    // ======================= COMPUTE WARPS (w < 4) =========================
    const int rbase = w * 16;                       // local row base of warp
    const int row0g = blockIdx.x * ROWS + rbase;    // global row base

    const int j  = lane & 7;
    const int gw = lane >> 3;                       // 0..3: row-in-pass

    // cross-wave L2 prefetch: warm the tile of the block that will occupy
    // this SM slot in the next wave (pure hint, fire-and-forget)
    {
        int pf = blockIdx.x + WAVE;
        if (pf * ROWS < B)
            l2_prefetch_tile(x, pf * ROWS, rbase, lane, B);
    }

    // ---- Phase 1: pre = x @ W1^T + b1; ping-pong pair pipeline ------------
    {
        u64 a01[4], a23[4];
        #pragma unroll
        for (int r = 0; r < 4; r++) { a01[r] = 0ull; a23[r] = 0ull; }

        bool ok[4];
        #pragma unroll
        for (int r = 0; r < 4; r++) ok[r] = (row0g + r * 4 + gw) < B;

        const float* xb = x + (size_t)(row0g + gw) * D_IN + j * 4;

        float4 xa0[4], xa1[4], xb0[4], xb1[4];

        LOAD_PAIR(xa0, xa1, 0);
        COMP_STEP(xa0, 0);  LOAD_PAIR(xb0, xb1, 1);  COMP_STEP(xa1, 1);
        COMP_STEP(xb0, 2);  LOAD_PAIR(xa0, xa1, 2);  COMP_STEP(xb1, 3);
        COMP_STEP(xa0, 4);  LOAD_PAIR(xb0, xb1, 3);  COMP_STEP(xa1, 5);
        COMP_STEP(xb0, 6);  COMP_STEP(xb1, 7);

        #pragma unroll
        for (int r = 0; r < 4; r++) {
            u64 v0 = a01[r], v1 = a23[r];
            #pragma unroll
            for (int off = 1; off < 8; off <<= 1) {
                v0 = fadd2(v0, __shfl_xor_sync(0xffffffffu, v0, off));
                v1 = fadd2(v1, __shfl_xor_sync(0xffffffffu, v1, off));
            }
            if (j == 0) {
                float p0, p1, p2, p3;
                unpack2(v0, p0, p1);
                unpack2(v1, p2, p3);
                fs[rbase + r * 4 + gw] = make_float4(p0 + b1s[0], p1 + b1s[1],
                                                     p2 + b1s[2], p3 + b1s[3]);
            }
        }
    }
    __syncwarp();                    // fs rows of THIS warp are visible

    // ---- Phase 2a (usx-free): tanh -> encode -> product state -------------
    const int lrow = rbase + (lane & 15);
    const int half = lane >> 4;
    u64 pp[16];
    {
        float4 f4 = fs[lrow];
        float fv[4];
        fv[0] = tanhf(f4.x) * PI_F;
        fv[1] = tanhf(f4.y) * PI_F;
        fv[2] = tanhf(f4.z) * PI_F;
        fv[3] = tanhf(f4.w) * PI_F;

        float ra[4]; float2 cb[4];
        #pragma unroll
        for (int i = 0; i < 4; i++) {
            float fi = fv[i];
            float c  = rsqrtf(fmaf(fi, fi, 1.f));   // cos(atan f)
            float fc = fi * c;                       // sin(atan f)
            float t0 = 0.5f - 0.5f * fc;
            float t1 = 0.5f + 0.5f * fc;
            ra[i]    = t0 * rsqrtf(t0);              // sqrt(t0)
            float a1 = t1 * rsqrtf(t1);
            float gg = fi * fi;
            float cp = rsqrtf(fmaf(gg, gg, 1.f));
            float mm = a1 * cp;
            cb[i] = make_float2(mm, mm * gg);        // a1 * e^{i phi}
        }

        float  p0  = ra[0] * ra[1];
        float2 p1  = make_float2(ra[0] * cb[1].x, ra[0] * cb[1].y);
        float2 p2  = make_float2(cb[0].x * ra[1], cb[0].y * ra[1]);
        float2 p3  = cmulf(cb[0], cb[1]);

        float  q0  = p0 * ra[2];
        float2 q1  = make_float2(p0 * cb[2].x, p0 * cb[2].y);
        float2 q2  = make_float2(p1.x * ra[2], p1.y * ra[2]);
        float2 q3  = cmulf(p1, cb[2]);
        float2 q4  = make_float2(p2.x * ra[2], p2.y * ra[2]);
        float2 q5  = cmulf(p2, cb[2]);
        float2 q6  = make_float2(p3.x * ra[2], p3.y * ra[2]);
        float2 q7  = cmulf(p3, cb[2]);

        float r3 = ra[3]; float2 c3 = cb[3];
        pp[ 0] = pack2(q0 * r3, 0.f);
        pp[ 1] = pack2(q0 * c3.x, q0 * c3.y);
        float2 e;
        e = make_float2(q1.x * r3, q1.y * r3);  pp[ 2] = pack2(e.x, e.y);
        e = cmulf(q1, c3);                      pp[ 3] = pack2(e.x, e.y);
        e = make_float2(q2.x * r3, q2.y * r3);  pp[ 4] = pack2(e.x, e.y);
        e = cmulf(q2, c3);                      pp[ 5] = pack2(e.x, e.y);
        e = make_float2(q3.x * r3, q3.y * r3);  pp[ 6] = pack2(e.x, e.y);
        e = cmulf(q3, c3);                      pp[ 7] = pack2(e.x, e.y);
        e = make_float2(q4.x * r3, q4.y * r3);  pp[ 8] = pack2(e.x, e.y);
        e = cmulf(q4, c3);                      pp[ 9] = pack2(e.x, e.y);
        e = make_float2(q5.x * r3, q5.y * r3);  pp[10] = pack2(e.x, e.y);
        e = cmulf(q5, c3);                      pp[11] = pack2(e.x, e.y);
        e = make_float2(q6.x * r3, q6.y * r3);  pp[12] = pack2(e.x, e.y);
        e = cmulf(q6, c3);                      pp[13] = pack2(e.x, e.y);
        e = make_float2(q7.x * r3, q7.y * r3);  pp[14] = pack2(e.x, e.y);
        e = cmulf(q7, c3);                      pp[15] = pack2(e.x, e.y);
    }
    __syncthreads();                 // barrier B: usx ready

    // ---- Phase 2b: packed matvec against usx -> signed |amp|^2 ------------
    {
        const int sbase = half * 8;
        float zs = 0.f, z1v = 0.f, z2v = 0.f, z3v = 0.f;
        #pragma unroll
        for (int k = 0; k < 8; k++) {
            const double2* urow = &usx[(sbase + k) * 16];
            u64 accA = 0ull, accB = 0ull;
            #pragma unroll
            for (int h = 0; h < 16; h++) {
                double2 uu = urow[h];
                u64 rr = __double_as_longlong(uu.x);
                u64 ii = __double_as_longlong(uu.y);
                accA = ffma2(rr, pp[h], accA);
                accB = ffma2(ii, pp[h], accB);
            }
            float Ax, Ay, Bx, By;
            unpack2(accA, Ax, Ay);
            unpack2(accB, Bx, By);
            float ar = Ax - By;
            float ai = Ay + Bx;
            float p  = fmaf(ar, ar, ai * ai);
            zs  += p;
            z1v += (k & 4) ? -p : p;
            z2v += (k & 2) ? -p : p;
            z3v += (k & 1) ? -p : p;
        }
        float z0v = half ? -zs : zs;
        qs2[lrow][half] = make_float4(z0v, z1v, z2v, z3v);
    }
    __syncwarp();

    // ---- Phase 3: out = q @ W2^T + b2, warp-local, coalesced --------------
    {
        const int o4 = (lane & 15) * 4;           // 4 consecutive output cols
        const int hb = lane >> 4;                 // 0..1: row-within-pair
        float4 w2r0 = __ldg((const float4*)(W2 + (size_t)(o4 + 0) * 4));
        float4 w2r1 = __ldg((const float4*)(W2 + (size_t)(o4 + 1) * 4));
        float4 w2r2 = __ldg((const float4*)(W2 + (size_t)(o4 + 2) * 4));
        float4 w2r3 = __ldg((const float4*)(W2 + (size_t)(o4 + 3) * 4));
        float4 b2v  = __ldg((const float4*)(b2 + o4));
        #pragma unroll
        for (int p = 0; p < 8; p++) {
            int lr  = rbase + p * 2 + hb;         // local row 0..63
            int row = blockIdx.x * ROWS + lr;
            if (row < B) {
                float4 qa = qs2[lr][0], qb = qs2[lr][1];
                float4 q4 = make_float4(qa.x + qb.x, qa.y + qb.y,
                                        qa.z + qb.z, qa.w + qb.w);
                float4 o;
                o.x = fmaf(q4.x, w2r0.x, fmaf(q4.y, w2r0.y, fmaf(q4.z, w2r0.z, fmaf(q4.w, w2r0.w, b2v.x))));
                o.y = fmaf(q4.x, w2r1.x, fmaf(q4.y, w2r1.y, fmaf(q4.z, w2r1.z, fmaf(q4.w, w2r1.w, b2v.y))));
                o.z = fmaf(q4.x, w2r2.x, fmaf(q4.y, w2r2.y, fmaf(q4.z, w2r2.z, fmaf(q4.w, w2r2.w, b2v.z))));
                o.w = fmaf(q4.x, w2r3.x, fmaf(q4.y, w2r3.y, fmaf(q4.z, w2r3.z, fmaf(q4.w, w2r3.w, b2v.w))));
                *(float4*)(out + (size_t)row * D_OUT + o4) = o;
            }
        }
    }
}

// ---------------------------------------------------------------------------
extern "C" void kernel_launch(void* const* d_in, const int* in_sizes, int n_in,
                              void* d_out, int out_size)
{
    (void)n_in; (void)out_size;
    const float* x       = (const float*)d_in[0];
    const float* W1      = (const float*)d_in[1];
    const float* b1      = (const float*)d_in[2];
    const float* weights = (const float*)d_in[3];
    const float* W2      = (const float*)d_in[4];
    const float* b2      = (const float*)d_in[5];
    float* out = (float*)d_out;

    int B        = in_sizes[0] / D_IN;
    int n_layers = in_sizes[3] / 12;

    int nb = (B + ROWS - 1) / ROWS;
    qproj_kernel<<<nb, THREADS>>>(x, W1, b1, weights, W2, b2, out, B, n_layers);
}

// round 16
// speedup vs baseline: 1.1463x; 1.1463x over previous
#include <cuda_runtime.h>
#include <math.h>

#define D_IN     256
#define D_OUT    64
#define THREADS  160          // 4 compute warps (64 rows) + 1 setup warp
#define ROWS     64
#define PI_F     3.14159265358979323846f

typedef unsigned long long u64;

// ---- packed f32x2 helpers (sm_100+) ---------------------------------------
static __device__ __forceinline__ u64 ffma2(u64 a, u64 b, u64 c) {
    u64 d; asm("fma.rn.f32x2 %0, %1, %2, %3;" : "=l"(d) : "l"(a), "l"(b), "l"(c)); return d;
}
static __device__ __forceinline__ u64 fadd2(u64 a, u64 b) {
    u64 d; asm("add.rn.f32x2 %0, %1, %2;" : "=l"(d) : "l"(a), "l"(b)); return d;
}
static __device__ __forceinline__ u64 pack2(float lo, float hi) {
    u64 d; asm("mov.b64 %0, {%1, %2};" : "=l"(d) : "f"(lo), "f"(hi)); return d;
}
static __device__ __forceinline__ void unpack2(u64 v, float& lo, float& hi) {
    asm("mov.b64 {%0, %1}, %2;" : "=f"(lo), "=f"(hi) : "l"(v));
}
static __device__ __forceinline__ float2 cmulf(float2 a, float2 b) {
    return make_float2(a.x * b.x - a.y * b.y, a.x * b.y + a.y * b.x);
}
static __device__ __forceinline__ float2 cmac2(float2 a, float2 b, float2 c, float2 d) {
    float re = a.x * b.x - a.y * b.y + c.x * d.x - c.y * d.y;
    float im = a.x * b.y + a.y * b.x + c.x * d.y + c.y * d.x;
    return make_float2(re, im);
}

// fast tanh via ex2: tanh|x| = (1-e)/(1+e), e = 2^(-2|x|*log2e). Branch-free,
// overflow-free (e in (0,1]); ~1e-7 rel err, 2 MUFU + few ALU.
static __device__ __forceinline__ float fast_tanh(float v) {
    float av = fabsf(v);
    float e;
    asm("ex2.approx.f32 %0, %1;" : "=f"(e) : "f"(av * -2.88539008178f));
    float r = __fdividef(1.f - e, 1.f + e);
    return copysignf(r, v);
}

// phase-1 helpers as macros (straightline, compile-time indices only)
#define LOAD_PAIR(B0, B1, MP)                                                 \
    do {                                                                      \
        _Pragma("unroll")                                                     \
        for (int r = 0; r < 4; r++) {                                         \
            B0[r] = make_float4(0.f, 0.f, 0.f, 0.f);                          \
            B1[r] = make_float4(0.f, 0.f, 0.f, 0.f);                          \
            if (ok[r]) {                                                      \
                const float* rp = xb + (size_t)(r * 4) * D_IN;                \
                B0[r] = __ldg((const float4*)(rp + (2 * (MP)) * 32));         \
                B1[r] = __ldg((const float4*)(rp + (2 * (MP) + 1) * 32));     \
            }                                                                 \
        }                                                                     \
    } while (0)

#define COMP_STEP(BUF, M)                                                     \
    do {                                                                      \
        const int c2 = (M) * 16 + j * 2;                                      \
        double2 wA = wps[0][c2], wA1 = wps[0][c2 + 1];                        \
        double2 wB = wps[1][c2], wB1 = wps[1][c2 + 1];                        \
        u64 w01_0 = __double_as_longlong(wA.x),  w01_1 = __double_as_longlong(wA.y);  \
        u64 w01_2 = __double_as_longlong(wA1.x), w01_3 = __double_as_longlong(wA1.y); \
        u64 w23_0 = __double_as_longlong(wB.x),  w23_1 = __double_as_longlong(wB.y);  \
        u64 w23_2 = __double_as_longlong(wB1.x), w23_3 = __double_as_longlong(wB1.y); \
        _Pragma("unroll")                                                     \
        for (int r = 0; r < 4; r++) {                                         \
            float4 xv = BUF[r];                                               \
            u64 x0 = pack2(xv.x, xv.x), x1 = pack2(xv.y, xv.y);               \
            u64 x2 = pack2(xv.z, xv.z), x3 = pack2(xv.w, xv.w);               \
            a01[r] = ffma2(x0, w01_0, a01[r]); a01[r] = ffma2(x1, w01_1, a01[r]); \
            a01[r] = ffma2(x2, w01_2, a01[r]); a01[r] = ffma2(x3, w01_3, a01[r]); \
            a23[r] = ffma2(x0, w23_0, a23[r]); a23[r] = ffma2(x1, w23_1, a23[r]); \
            a23[r] = ffma2(x2, w23_2, a23[r]); a23[r] = ffma2(x3, w23_3, a23[r]); \
        }                                                                     \
    } while (0)

// ---------------------------------------------------------------------------
// Fused kernel, warp-specialized; phase-1 x loads via ping-pong pair pipeline
// (two named buffer pairs, hand-unrolled; each LDG gets 1-2 compute-steps of
// lead time):
//   barrier A: wps ready. Between A and B: warp 4 builds usx || warps 0..3
//   run phase 1. barrier B: usx ready. Phases 2+3 warp-local; warp 4 returns.
// ---------------------------------------------------------------------------
__global__ __launch_bounds__(THREADS, 5)
void qproj_kernel(const float* __restrict__ x,  const float* __restrict__ W1,
                  const float* __restrict__ b1, const float* __restrict__ weights,
                  const float* __restrict__ W2, const float* __restrict__ b2,
                  float* __restrict__ out, int B, int n_layers)
{
    __shared__ double2 usx[256];      // expanded U: ((re,re),(im,im)), 4 KB
    __shared__ double2 wps[2][128];   // pair-packed W1, 2 KB
    __shared__ float4  fs[ROWS];      // pre-activation per row
    __shared__ float4  qs2[ROWS][2];  // partial <Z_i> per row, per half
    __shared__ float   b1s[4];

    const int t = threadIdx.x;
    if (t < 128) {
        // pair-packed weights: thread t owns columns 2t, 2t+1
        int c = t * 2;
        float a00 = __ldg(&W1[0 * D_IN + c]), a01 = __ldg(&W1[0 * D_IN + c + 1]);
        float a10 = __ldg(&W1[1 * D_IN + c]), a11 = __ldg(&W1[1 * D_IN + c + 1]);
        float a20 = __ldg(&W1[2 * D_IN + c]), a21 = __ldg(&W1[2 * D_IN + c + 1]);
        float a30 = __ldg(&W1[3 * D_IN + c]), a31 = __ldg(&W1[3 * D_IN + c + 1]);
        wps[0][t] = make_double2(__longlong_as_double((long long)pack2(a00, a10)),
                                 __longlong_as_double((long long)pack2(a01, a11)));
        wps[1][t] = make_double2(__longlong_as_double((long long)pack2(a20, a30)),
                                 __longlong_as_double((long long)pack2(a21, a31)));
        if (t < 4) b1s[t] = b1[t];
    }
    __syncthreads();                 // barrier A

    const int w    = t >> 5;         // warp id 0..4
    const int lane = t & 31;

    if (w == 4) {
        // =================== SETUP WARP: build usx =========================
        if (lane < 16) {
            const int j = lane;
            float2 uc[16];
            #pragma unroll
            for (int s = 0; s < 16; s++)
                uc[s] = make_float2(s == j ? 1.f : 0.f, 0.f);

            for (int l = 0; l < n_layers; l++) {
                const int SIG[16] = {0,6,12,10,11,13,7,1,15,9,3,5,4,2,8,14};
                float2 tv[16];
                #pragma unroll
                for (int s = 0; s < 16; s++) tv[s] = uc[SIG[s]];
                #pragma unroll
                for (int s = 0; s < 16; s++) uc[s] = tv[s];
                #pragma unroll
                for (int i = 0; i < 4; i++) {
                    float phi = __ldg(&weights[(l * 4 + i) * 3 + 0]);
                    float th  = __ldg(&weights[(l * 4 + i) * 3 + 1]);
                    float om  = __ldg(&weights[(l * 4 + i) * 3 + 2]);
                    float st, ct;  __sincosf(0.5f * th, &st, &ct);
                    float sa, ca;  __sincosf(0.5f * (phi + om), &sa, &ca);
                    float sb, cb;  __sincosf(0.5f * (phi - om), &sb, &cb);
                    float2 U00 = make_float2( ct * ca, -ct * sa);
                    float2 U01 = make_float2(-st * cb, -st * sb);
                    float2 U10 = make_float2( st * cb, -st * sb);
                    float2 U11 = make_float2( ct * ca,  ct * sa);
                    const int b = 3 - i, m = 1 << b;
                    #pragma unroll
                    for (int s = 0; s < 16; s++) {
                        if (!((s >> b) & 1)) {
                            float2 a0 = uc[s], a1 = uc[s | m];
                            uc[s]     = cmac2(U00, a0, U01, a1);
                            uc[s | m] = cmac2(U10, a0, U11, a1);
                        }
                    }
                }
            }
            #pragma unroll
            for (int s = 0; s < 16; s++)
                ((float4*)usx)[s * 16 + j] =
                    make_float4(uc[s].x, uc[s].x, uc[s].y, uc[s].y);
        }
        __syncthreads();             // barrier B: usx published
        return;
    }

    // ======================= COMPUTE WARPS (w < 4) =========================
    const int rbase = w * 16;                       // local row base of warp
    const int row0g = blockIdx.x * ROWS + rbase;    // global row base

    const int j  = lane & 7;
    const int gw = lane >> 3;                       // 0..3: row-in-pass

    // ---- Phase 1: pre = x @ W1^T + b1; ping-pong pair pipeline ------------
    {
        u64 a01[4], a23[4];
        #pragma unroll
        for (int r = 0; r < 4; r++) { a01[r] = 0ull; a23[r] = 0ull; }

        bool ok[4];
        #pragma unroll
        for (int r = 0; r < 4; r++) ok[r] = (row0g + r * 4 + gw) < B;

        const float* xb = x + (size_t)(row0g + gw) * D_IN + j * 4;

        float4 xa0[4], xa1[4], xb0[4], xb1[4];

        LOAD_PAIR(xa0, xa1, 0);
        COMP_STEP(xa0, 0);  LOAD_PAIR(xb0, xb1, 1);  COMP_STEP(xa1, 1);
        COMP_STEP(xb0, 2);  LOAD_PAIR(xa0, xa1, 2);  COMP_STEP(xb1, 3);
        COMP_STEP(xa0, 4);  LOAD_PAIR(xb0, xb1, 3);  COMP_STEP(xa1, 5);
        COMP_STEP(xb0, 6);  COMP_STEP(xb1, 7);

        #pragma unroll
        for (int r = 0; r < 4; r++) {
            u64 v0 = a01[r], v1 = a23[r];
            #pragma unroll
            for (int off = 1; off < 8; off <<= 1) {
                v0 = fadd2(v0, __shfl_xor_sync(0xffffffffu, v0, off));
                v1 = fadd2(v1, __shfl_xor_sync(0xffffffffu, v1, off));
            }
            if (j == 0) {
                float p0, p1, p2, p3;
                unpack2(v0, p0, p1);
                unpack2(v1, p2, p3);
                fs[rbase + r * 4 + gw] = make_float4(p0 + b1s[0], p1 + b1s[1],
                                                     p2 + b1s[2], p3 + b1s[3]);
            }
        }
    }
    __syncthreads();                 // barrier B: usx ready (fs also visible)

    // ---- Phase 2: tanh -> encode -> product state -> packed matvec --------
    {
        const int lrow = rbase + (lane & 15);
        const int half = lane >> 4;
        float4 f4 = fs[lrow];
        float fv[4];
        fv[0] = fast_tanh(f4.x) * PI_F;
        fv[1] = fast_tanh(f4.y) * PI_F;
        fv[2] = fast_tanh(f4.z) * PI_F;
        fv[3] = fast_tanh(f4.w) * PI_F;

        float ra[4]; float2 cb[4];
        #pragma unroll
        for (int i = 0; i < 4; i++) {
            float fi = fv[i];
            float c  = rsqrtf(fmaf(fi, fi, 1.f));   // cos(atan f)
            float fc = fi * c;                       // sin(atan f)
            float t0 = 0.5f - 0.5f * fc;
            float t1 = 0.5f + 0.5f * fc;
            ra[i]    = t0 * rsqrtf(t0);              // sqrt(t0)
            float a1 = t1 * rsqrtf(t1);
            float gg = fi * fi;
            float cp = rsqrtf(fmaf(gg, gg, 1.f));
            float mm = a1 * cp;
            cb[i] = make_float2(mm, mm * gg);        // a1 * e^{i phi}
        }

        float  p0  = ra[0] * ra[1];
        float2 p1  = make_float2(ra[0] * cb[1].x, ra[0] * cb[1].y);
        float2 p2  = make_float2(cb[0].x * ra[1], cb[0].y * ra[1]);
        float2 p3  = cmulf(cb[0], cb[1]);

        float  q0  = p0 * ra[2];
        float2 q1  = make_float2(p0 * cb[2].x, p0 * cb[2].y);
        float2 q2  = make_float2(p1.x * ra[2], p1.y * ra[2]);
        float2 q3  = cmulf(p1, cb[2]);
        float2 q4  = make_float2(p2.x * ra[2], p2.y * ra[2]);
        float2 q5  = cmulf(p2, cb[2]);
        float2 q6  = make_float2(p3.x * ra[2], p3.y * ra[2]);
        float2 q7  = cmulf(p3, cb[2]);

        u64 pp[16];
        {
            float r3 = ra[3]; float2 c3 = cb[3];
            pp[ 0] = pack2(q0 * r3, 0.f);
            pp[ 1] = pack2(q0 * c3.x, q0 * c3.y);
            float2 e;
            e = make_float2(q1.x * r3, q1.y * r3);  pp[ 2] = pack2(e.x, e.y);
            e = cmulf(q1, c3);                      pp[ 3] = pack2(e.x, e.y);
            e = make_float2(q2.x * r3, q2.y * r3);  pp[ 4] = pack2(e.x, e.y);
            e = cmulf(q2, c3);                      pp[ 5] = pack2(e.x, e.y);
            e = make_float2(q3.x * r3, q3.y * r3);  pp[ 6] = pack2(e.x, e.y);
            e = cmulf(q3, c3);                      pp[ 7] = pack2(e.x, e.y);
            e = make_float2(q4.x * r3, q4.y * r3);  pp[ 8] = pack2(e.x, e.y);
            e = cmulf(q4, c3);                      pp[ 9] = pack2(e.x, e.y);
            e = make_float2(q5.x * r3, q5.y * r3);  pp[10] = pack2(e.x, e.y);
            e = cmulf(q5, c3);                      pp[11] = pack2(e.x, e.y);
            e = make_float2(q6.x * r3, q6.y * r3);  pp[12] = pack2(e.x, e.y);
            e = cmulf(q6, c3);                      pp[13] = pack2(e.x, e.y);
            e = make_float2(q7.x * r3, q7.y * r3);  pp[14] = pack2(e.x, e.y);
            e = cmulf(q7, c3);                      pp[15] = pack2(e.x, e.y);
        }

        const int sbase = half * 8;
        float zs = 0.f, z1v = 0.f, z2v = 0.f, z3v = 0.f;
        #pragma unroll
        for (int k = 0; k < 8; k++) {
            const double2* urow = &usx[(sbase + k) * 16];
            u64 accA = 0ull, accB = 0ull;
            #pragma unroll
            for (int h = 0; h < 16; h++) {
                double2 uu = urow[h];
                u64 rr = __double_as_longlong(uu.x);
                u64 ii = __double_as_longlong(uu.y);
                accA = ffma2(rr, pp[h], accA);
                accB = ffma2(ii, pp[h], accB);
            }
            float Ax, Ay, Bx, By;
            unpack2(accA, Ax, Ay);
            unpack2(accB, Bx, By);
            float ar = Ax - By;
            float ai = Ay + Bx;
            float p  = fmaf(ar, ar, ai * ai);
            zs  += p;
            z1v += (k & 4) ? -p : p;
            z2v += (k & 2) ? -p : p;
            z3v += (k & 1) ? -p : p;
        }
        float z0v = half ? -zs : zs;
        qs2[lrow][half] = make_float4(z0v, z1v, z2v, z3v);
    }
    __syncwarp();

    // ---- Phase 3: out = q @ W2^T + b2, warp-local, coalesced --------------
    {
        const int o4 = (lane & 15) * 4;           // 4 consecutive output cols
        const int hb = lane >> 4;                 // 0..1: row-within-pair
        float4 w2r0 = __ldg((const float4*)(W2 + (size_t)(o4 + 0) * 4));
        float4 w2r1 = __ldg((const float4*)(W2 + (size_t)(o4 + 1) * 4));
        float4 w2r2 = __ldg((const float4*)(W2 + (size_t)(o4 + 2) * 4));
        float4 w2r3 = __ldg((const float4*)(W2 + (size_t)(o4 + 3) * 4));
        float4 b2v  = __ldg((const float4*)(b2 + o4));
        #pragma unroll
        for (int p = 0; p < 8; p++) {
            int lr  = rbase + p * 2 + hb;         // local row 0..63
            int row = blockIdx.x * ROWS + lr;
            if (row < B) {
                float4 qa = qs2[lr][0], qb = qs2[lr][1];
                float4 q4 = make_float4(qa.x + qb.x, qa.y + qb.y,
                                        qa.z + qb.z, qa.w + qb.w);
                float4 o;
                o.x = fmaf(q4.x, w2r0.x, fmaf(q4.y, w2r0.y, fmaf(q4.z, w2r0.z, fmaf(q4.w, w2r0.w, b2v.x))));
                o.y = fmaf(q4.x, w2r1.x, fmaf(q4.y, w2r1.y, fmaf(q4.z, w2r1.z, fmaf(q4.w, w2r1.w, b2v.y))));
                o.z = fmaf(q4.x, w2r2.x, fmaf(q4.y, w2r2.y, fmaf(q4.z, w2r2.z, fmaf(q4.w, w2r2.w, b2v.z))));
                o.w = fmaf(q4.x, w2r3.x, fmaf(q4.y, w2r3.y, fmaf(q4.z, w2r3.z, fmaf(q4.w, w2r3.w, b2v.w))));
                *(float4*)(out + (size_t)row * D_OUT + o4) = o;
            }
        }
    }
}

// ---------------------------------------------------------------------------
extern "C" void kernel_launch(void* const* d_in, const int* in_sizes, int n_in,
                              void* d_out, int out_size)
{
    (void)n_in; (void)out_size;
    const float* x       = (const float*)d_in[0];
    const float* W1      = (const float*)d_in[1];
    const float* b1      = (const float*)d_in[2];
    const float* weights = (const float*)d_in[3];
    const float* W2      = (const float*)d_in[4];
    const float* b2      = (const float*)d_in[5];
    float* out = (float*)d_out;

    int B        = in_sizes[0] / D_IN;
    int n_layers = in_sizes[3] / 12;

    int nb = (B + ROWS - 1) / ROWS;
    qproj_kernel<<<nb, THREADS>>>(x, W1, b1, weights, W2, b2, out, B, n_layers);
}